// round 12
// baseline (speedup 1.0000x reference)
#include <cuda_runtime.h>
#include <cuda_fp16.h>
#include <mma.h>
#include <cstdint>

using namespace nvcuda;

#define MAX_N   100000
#define MAX_E   1600000
#define NG      256
#define DHID    64
#define NBLK_MAX 128   // ceil(MAX_N/1024) = 98 < 128

// Scratch (allocation-free rule: __device__ globals).
__device__ uint2 g_bufA[(size_t)MAX_N * 16];     // fp16 rows: m1, later h2
__device__ uint2 g_bufB[(size_t)MAX_N * 16];     // fp16 rows: relu(h1)
__device__ uint2 g_bufC[(size_t)MAX_N * 16];     // fp16 rows: agg(r1)
__device__ float g_pool[NG * DHID];
__device__ float g_cnt[NG];
__device__ float g_wc[DHID * 16];                 // W3 @ Wlin (64x16)
__device__ int   g_is64;                          // 1 if indices are int64
__device__ int   g_deg[MAX_N];                    // in-degree histogram
__device__ int   g_rowptr[MAX_N + 1];             // CSR row pointers (by dst)
__device__ int   g_wptr[MAX_N];                   // fill cursors
__device__ __align__(16) int g_col[MAX_E];        // CSR: src node per edge slot
__device__ int   g_bsum[NBLK_MAX];                // per-block partial sums
__device__ int   g_gptr[NG + 1];                  // edge-slot range per graph

__device__ __forceinline__ int load_idx(const void* p, size_t i, int is64) {
    if (is64) return (int)(((const long long*)p)[i]);
    return ((const int*)p)[i];
}

// ---------------------------------------------------------------------------
// K1: block 0 detects index dtype (int64 values < 2^31 have zero odd words);
// other blocks zero g_deg, g_pool, g_cnt.
// ---------------------------------------------------------------------------
__global__ void init_kernel(const unsigned int* __restrict__ w, int n) {
    if (blockIdx.x == 0) {
        __shared__ unsigned int s;
        if (threadIdx.x == 0) s = 0u;
        __syncthreads();
        unsigned int v = 0u;
        for (int i = threadIdx.x; i < 1024; i += 256) v |= w[2 * i + 1];
        atomicOr(&s, v);
        __syncthreads();
        if (threadIdx.x == 0) g_is64 = (s == 0u) ? 1 : 0;
        return;
    }
    int t = (blockIdx.x - 1) * 256 + threadIdx.x;
    if (t < n) g_deg[t] = 0;
    float4 z = make_float4(0.f, 0.f, 0.f, 0.f);
    if (t < NG * 16) reinterpret_cast<float4*>(g_pool)[t] = z;
    if (t < NG / 4)  reinterpret_cast<float4*>(g_cnt)[t] = z;
}

// ---------------------------------------------------------------------------
// K2: fused small independent work: dst histogram | graph counts | Wc.
// ---------------------------------------------------------------------------
__global__ void __launch_bounds__(256) misc_kernel(
    const float* __restrict__ W3, const float* __restrict__ Wlin,
    const void* __restrict__ ei, const void* __restrict__ bat,
    int n, int E, int histB, int cntB)
{
    int b = blockIdx.x;
    if (b < histB) {
        int e = b * 256 + threadIdx.x;
        if (e < E) {
            int d = load_idx(ei, (size_t)E + e, g_is64);
            atomicAdd(&g_deg[d], 1);
        }
        return;
    }
    b -= histB;
    if (b < cntB) {
        int t = b * 256 + threadIdx.x;
        if (t < n) {
            int g = load_idx(bat, (size_t)t, g_is64);
            atomicAdd(&g_cnt[g], 1.0f);
        }
        return;
    }
    b -= cntB;
    int t = b * 256 + threadIdx.x;
    if (t < DHID * 16) {
        int i = t >> 4, o = t & 15;
        float acc = 0.f;
        #pragma unroll
        for (int k = 0; k < 64; k++)
            acc = fmaf(W3[i * 64 + k], Wlin[k * 16 + o], acc);
        g_wc[t] = acc;
    }
}

// ---------------------------------------------------------------------------
// Tensor-core matmul: out_fp16[n,64] = fp16( maybe_relu( A[n,K] @ W[K,64] ) )
// Block = 256 threads (8 warps) handles 128 rows. wmma m16n16k16, fp32 acc.
// ---------------------------------------------------------------------------
template <int K, bool A_HALF, bool RELU_OUT>
__global__ void __launch_bounds__(256) mmw_kernel(const void* __restrict__ A,
                                                  const float* __restrict__ W,
                                                  uint2* __restrict__ out,
                                                  int n) {
    __shared__ __align__(32) char raw[32768 + K * 64 * 2];
    half*  sA = reinterpret_cast<half*>(raw);
    half*  sB = reinterpret_cast<half*>(raw + 32768);
    float* sC = reinterpret_cast<float*>(raw);

    const int tid = threadIdx.x;
    const int rowbase = blockIdx.x * 128;

    const float2* W2p = reinterpret_cast<const float2*>(W);
    for (int i = tid; i < K * 32; i += 256) {
        float2 v = W2p[i];
        reinterpret_cast<half2*>(sB)[i] = __floats2half2_rn(v.x, v.y);
    }

    if (A_HALF) {
        const uint4* A4 = reinterpret_cast<const uint4*>(A);
        constexpr int RW = K / 8;
        for (int i = tid; i < 128 * RW; i += 256) {
            int r = i / RW;
            int gr = rowbase + r;
            uint4 v = make_uint4(0u, 0u, 0u, 0u);
            if (gr < n) v = A4[(size_t)gr * RW + (i % RW)];
            reinterpret_cast<uint4*>(sA)[i] = v;
        }
    } else {
        const float4* A4 = reinterpret_cast<const float4*>(A);
        constexpr int RW = K / 4;
        for (int i = tid; i < 128 * RW; i += 256) {
            int r = i / RW;
            int gr = rowbase + r;
            float4 v = make_float4(0.f, 0.f, 0.f, 0.f);
            if (gr < n) v = A4[(size_t)gr * RW + (i % RW)];
            reinterpret_cast<half2*>(sA)[i * 2]     = __floats2half2_rn(v.x, v.y);
            reinterpret_cast<half2*>(sA)[i * 2 + 1] = __floats2half2_rn(v.z, v.w);
        }
    }
    __syncthreads();

    const int w = tid >> 5;
    wmma::fragment<wmma::accumulator, 16, 16, 16, float> c[4];
    #pragma unroll
    for (int nf = 0; nf < 4; nf++) wmma::fill_fragment(c[nf], 0.f);

    #pragma unroll
    for (int k = 0; k < K / 16; k++) {
        wmma::fragment<wmma::matrix_a, 16, 16, 16, half, wmma::row_major> a;
        wmma::load_matrix_sync(a, sA + (w * 16) * K + k * 16, K);
        #pragma unroll
        for (int nf = 0; nf < 4; nf++) {
            wmma::fragment<wmma::matrix_b, 16, 16, 16, half, wmma::row_major> bfr;
            wmma::load_matrix_sync(bfr, sB + (k * 16) * 64 + nf * 16, 64);
            wmma::mma_sync(c[nf], a, bfr, c[nf]);
        }
    }
    __syncthreads();

    #pragma unroll
    for (int nf = 0; nf < 4; nf++)
        wmma::store_matrix_sync(sC + (w * 16) * 64 + nf * 16, c[nf], 64,
                                wmma::mem_row_major);
    __syncthreads();

    for (int i = tid; i < 128 * 16; i += 256) {
        int r = i >> 4, cg = i & 15;
        int gr = rowbase + r;
        if (gr >= n) continue;
        float4 v = reinterpret_cast<const float4*>(sC)[r * 16 + cg];
        if (RELU_OUT) {
            v.x = fmaxf(v.x, 0.f); v.y = fmaxf(v.y, 0.f);
            v.z = fmaxf(v.z, 0.f); v.w = fmaxf(v.w, 0.f);
        }
        __half2 p0 = __floats2half2_rn(v.x, v.y);
        __half2 p1 = __floats2half2_rn(v.z, v.w);
        out[(size_t)gr * 16 + cg] =
            make_uint2(*reinterpret_cast<unsigned*>(&p0), *reinterpret_cast<unsigned*>(&p1));
    }
}

// ---------------------------------------------------------------------------
// CSR scan stage 1: per-block sums over 1024-element chunks of g_deg.
// ---------------------------------------------------------------------------
__global__ void __launch_bounds__(256) blocksum_kernel(int n) {
    __shared__ int wsum[8];
    int tid = threadIdx.x;
    int base = blockIdx.x * 1024 + tid * 4;
    int s = 0;
    #pragma unroll
    for (int k = 0; k < 4; k++)
        if (base + k < n) s += g_deg[base + k];
    #pragma unroll
    for (int off = 16; off > 0; off >>= 1)
        s += __shfl_down_sync(0xffffffffu, s, off);
    if ((tid & 31) == 0) wsum[tid >> 5] = s;
    __syncthreads();
    if (tid == 0) {
        int t = 0;
        #pragma unroll
        for (int i = 0; i < 8; i++) t += wsum[i];
        g_bsum[blockIdx.x] = t;
    }
}

// ---------------------------------------------------------------------------
// CSR scan stage 2 (fused): block-prefix of g_bsum + local rescan -> rowptr.
// ---------------------------------------------------------------------------
__global__ void __launch_bounds__(256) writeptr_kernel(int n, int E) {
    __shared__ int tsum[256];
    __shared__ int sboff;
    int tid = threadIdx.x;

    {
        int partial = 0;
        for (int i = tid; i < blockIdx.x; i += 256) partial += g_bsum[i];
        #pragma unroll
        for (int off = 16; off > 0; off >>= 1)
            partial += __shfl_down_sync(0xffffffffu, partial, off);
        __shared__ int wsum[8];
        if ((tid & 31) == 0) wsum[tid >> 5] = partial;
        __syncthreads();
        if (tid == 0) {
            int t = 0;
            #pragma unroll
            for (int i = 0; i < 8; i++) t += wsum[i];
            sboff = t;
        }
    }

    int base = blockIdx.x * 1024 + tid * 4;
    int d[4];
    int s = 0;
    #pragma unroll
    for (int k = 0; k < 4; k++) {
        d[k] = (base + k < n) ? g_deg[base + k] : 0;
        s += d[k];
    }
    tsum[tid] = s;
    __syncthreads();
    for (int off = 1; off < 256; off <<= 1) {
        int v = (tid >= off) ? tsum[tid - off] : 0;
        __syncthreads();
        tsum[tid] += v;
        __syncthreads();
    }
    int run = ((tid > 0) ? tsum[tid - 1] : 0) + sboff;
    #pragma unroll
    for (int k = 0; k < 4; k++) {
        if (base + k < n) {
            g_rowptr[base + k] = run;
            g_wptr[base + k]   = run;
            run += d[k];
        }
    }
    if (blockIdx.x == 0 && tid == 0) g_rowptr[n] = E;
}

__global__ void __launch_bounds__(256) fill_kernel(const void* __restrict__ ei, int E) {
    int e = blockIdx.x * blockDim.x + threadIdx.x;
    if (e >= E) return;
    int is64 = g_is64;
    int s = load_idx(ei, (size_t)e, is64);
    int d = load_idx(ei, (size_t)E + e, is64);
    int pos = atomicAdd(&g_wptr[d], 1);
    g_col[pos] = s;
}

// ---------------------------------------------------------------------------
// gptr_kernel: g_gptr[g] = rowptr[first node with batch >= g]; gptr[NG] = E.
// One block of NG threads; binary search over sorted batch.
// ---------------------------------------------------------------------------
__global__ void __launch_bounds__(NG) gptr_kernel(const void* __restrict__ bat,
                                                  int n, int E) {
    int g = threadIdx.x;
    int is64 = g_is64;
    int lo = 0, hi = n;
    while (lo < hi) {
        int mid = (lo + hi) >> 1;
        if (load_idx(bat, (size_t)mid, is64) < g) lo = mid + 1; else hi = mid;
    }
    g_gptr[g] = g_rowptr[lo];
    if (g == 0) g_gptr[NG] = E;
}

// ---------------------------------------------------------------------------
// Gather core (R9-proven): 16 lanes/node, uint2 per lane, int4 index loads,
// fp16 pairwise tree per 4 edges, fp32 accumulate.
// ---------------------------------------------------------------------------
__device__ __forceinline__ __half2 u2h(unsigned u) {
    return *reinterpret_cast<__half2*>(&u);
}

__device__ __forceinline__ void acc_u2(float4& acc, uint2 u) {
    float2 f0 = __half22float2(u2h(u.x));
    float2 f1 = __half22float2(u2h(u.y));
    acc.x += f0.x; acc.y += f0.y; acc.z += f1.x; acc.w += f1.y;
}

// Accumulate edge slots [e, lim) for feature lane j.
__device__ __forceinline__ void acc_range(float4& acc, const uint2* __restrict__ m,
                                          int e, int lim, int j) {
    int alim = (e + 3) & ~3;
    if (alim > lim) alim = lim;
    for (; e < alim; e++)
        acc_u2(acc, m[(size_t)g_col[e] * 16 + j]);
    for (; e + 4 <= lim; e += 4) {
        int4 s4 = *reinterpret_cast<const int4*>(g_col + e);
        uint2 u0 = m[(size_t)s4.x * 16 + j];
        uint2 u1 = m[(size_t)s4.y * 16 + j];
        uint2 u2 = m[(size_t)s4.z * 16 + j];
        uint2 u3 = m[(size_t)s4.w * 16 + j];
        __half2 a = __hadd2(__hadd2(u2h(u0.x), u2h(u1.x)),
                            __hadd2(u2h(u2.x), u2h(u3.x)));
        __half2 b = __hadd2(__hadd2(u2h(u0.y), u2h(u1.y)),
                            __hadd2(u2h(u2.y), u2h(u3.y)));
        float2 f0 = __half22float2(a);
        float2 f1 = __half22float2(b);
        acc.x += f0.x; acc.y += f0.y; acc.z += f1.x; acc.w += f1.y;
    }
    for (; e < lim; e++)
        acc_u2(acc, m[(size_t)g_col[e] * 16 + j]);
}

// ---------------------------------------------------------------------------
// gather_kernel<MODE>: 16 lanes/node (R9 shape).
// MODE 0: out16[node] = fp16(agg)         (layer 2 input, bufC)
// MODE 1: out16[node] = fp16(relu(agg))   (layer 1 epilogue)
// ---------------------------------------------------------------------------
template <int MODE>
__global__ void __launch_bounds__(256) gather_kernel(const uint2* __restrict__ m,
                                                     uint2* __restrict__ out16,
                                                     int n) {
    int t = blockIdx.x * blockDim.x + threadIdx.x;
    int node = t >> 4;
    if (node >= n) return;
    int j = t & 15;

    float4 acc = make_float4(0.f, 0.f, 0.f, 0.f);
    acc_range(acc, m, g_rowptr[node], g_rowptr[node + 1], j);

    if (MODE == 1) {
        acc.x = fmaxf(acc.x, 0.f); acc.y = fmaxf(acc.y, 0.f);
        acc.z = fmaxf(acc.z, 0.f); acc.w = fmaxf(acc.w, 0.f);
    }
    __half2 p0 = __floats2half2_rn(acc.x, acc.y);
    __half2 p1 = __floats2half2_rn(acc.z, acc.w);
    out16[(size_t)node * 16 + j] =
        make_uint2(*reinterpret_cast<unsigned*>(&p0), *reinterpret_cast<unsigned*>(&p1));
}

// ---------------------------------------------------------------------------
// segsum_kernel (layer 3 + pool): edge slots are contiguous per graph (batch
// sorted + dst-ordered CSR). Each 16-lane group takes a fixed chunk of edge
// slots, accumulates h2[col[e]] in fp32, and red-adds to pool[g] only at
// graph boundaries. Perfectly balanced; no per-node rowptr reads.
// ---------------------------------------------------------------------------
__global__ void __launch_bounds__(256) segsum_kernel(const uint2* __restrict__ m,
                                                     int E, int ngroups) {
    __shared__ int sg[NG + 1];
    for (int i = threadIdx.x; i <= NG; i += 256) sg[i] = g_gptr[i];
    __syncthreads();

    int group = blockIdx.x * 16 + (threadIdx.x >> 4);
    int j = threadIdx.x & 15;
    if (group >= ngroups) return;

    int chunk = (E + ngroups - 1) / ngroups;
    int c0 = min(E, group * chunk);
    int c1 = min(E, c0 + chunk);
    if (c0 >= c1) return;

    // Largest g in [0, NG-1] with sg[g] <= c0  (then sg[g+1] > c0).
    int lo = 0, hi = NG - 1;
    while (lo < hi) {
        int mid = (lo + hi + 1) >> 1;
        if (sg[mid] <= c0) lo = mid; else hi = mid - 1;
    }
    int gcur = lo;

    float4 acc = make_float4(0.f, 0.f, 0.f, 0.f);
    int e = c0;
    bool pending = false;
    while (e < c1) {
        int segend = sg[gcur + 1];
        int lim = min(c1, segend);
        acc_range(acc, m, e, lim, j);
        e = lim;
        pending = true;
        if (lim == segend) {
            float* dst = g_pool + gcur * 64 + j * 4;
            asm volatile("red.global.add.v4.f32 [%0], {%1,%2,%3,%4};"
                         :: "l"(dst), "f"(acc.x), "f"(acc.y), "f"(acc.z), "f"(acc.w)
                         : "memory");
            acc = make_float4(0.f, 0.f, 0.f, 0.f);
            pending = false;
            gcur++;
            while (gcur < NG && sg[gcur + 1] <= e) gcur++;
        }
    }
    if (pending) {
        float* dst = g_pool + gcur * 64 + j * 4;
        asm volatile("red.global.add.v4.f32 [%0], {%1,%2,%3,%4};"
                     :: "l"(dst), "f"(acc.x), "f"(acc.y), "f"(acc.z), "f"(acc.w)
                     : "memory");
    }
}

// ---------------------------------------------------------------------------
// Head: out[g,o] = (pool[g,:]/max(cnt,1)) @ Wc[:,o]   -> [256,16]
// ---------------------------------------------------------------------------
__global__ void final_kernel(float* __restrict__ out) {
    int t = blockIdx.x * blockDim.x + threadIdx.x;
    if (t >= NG * 16) return;
    int g = t >> 4, o = t & 15;
    float inv = 1.0f / fmaxf(g_cnt[g], 1.0f);
    float acc = 0.f;
    #pragma unroll
    for (int k = 0; k < 64; k++)
        acc = fmaf(g_pool[g * 64 + k], g_wc[k * 16 + o], acc);
    out[t] = acc * inv;
}

// ---------------------------------------------------------------------------
extern "C" void kernel_launch(void* const* d_in, const int* in_sizes, int n_in,
                              void* d_out, int out_size) {
    const float* x    = (const float*)d_in[0];
    const float* W1   = (const float*)d_in[1];
    const float* W2   = (const float*)d_in[2];
    const float* W3   = (const float*)d_in[3];
    const float* Wlin = (const float*)d_in[4];
    const void*  ei   = d_in[5];
    const void*  bat  = d_in[6];

    const int n = in_sizes[0] / 128;   // nodes
    const int E = in_sizes[5] / 2;     // edges

    uint2 *d_bufA, *d_bufB, *d_bufC;
    cudaGetSymbolAddress((void**)&d_bufA, g_bufA);
    cudaGetSymbolAddress((void**)&d_bufB, g_bufB);
    cudaGetSymbolAddress((void**)&d_bufC, g_bufC);

    const int mmw_blocks = (n + 127) / 128;
    const int e_blocks   = (E + 255) / 256;
    const int cnt_blocks = (n + 255) / 256;
    const int g_blocks   = (n * 16 + 255) / 256;   // 16 lanes/node
    const int nblk       = (n + 1023) / 1024;
    const int ngroups    = (E + 511) / 512;        // ~512 edges per group
    const int seg_blocks = (ngroups + 15) / 16;

    // K1: detect dtype + zero deg/pool/cnt.
    init_kernel<<<1 + cnt_blocks, 256>>>((const unsigned int*)ei, n);

    // mm1 on tensor cores (independent of CSR).
    mmw_kernel<128, false, false><<<mmw_blocks, 256>>>(x, W1, d_bufA, n);

    // K2: hist | count | Wc.
    misc_kernel<<<e_blocks + cnt_blocks + 4, 256>>>(
        W3, Wlin, ei, bat, n, E, e_blocks, cnt_blocks);

    // CSR scan (2 stages) + graph edge ranges + fill.
    blocksum_kernel<<<nblk, 256>>>(n);
    writeptr_kernel<<<nblk, 256>>>(n, E);
    gptr_kernel<<<1, NG>>>(bat, n, E);
    fill_kernel<<<e_blocks, 256>>>(ei, E);

    // Layer 1: r1 = fp16(relu(agg(m1)))
    gather_kernel<1><<<g_blocks, 256>>>(d_bufA, d_bufB, n);

    // Layer 2: t2 = fp16(agg(r1)); h2 = fp16(relu(t2 @ W2)) on tensor cores
    gather_kernel<0><<<g_blocks, 256>>>(d_bufB, d_bufC, n);
    mmw_kernel<64, true, true><<<mmw_blocks, 256>>>(d_bufC, W2, d_bufA, n);

    // Layer 3 + pool: balanced segment sum over contiguous per-graph slots.
    segsum_kernel<<<seg_blocks, 256>>>(d_bufA, E, ngroups);

    // Head: out = (pool/cnt) @ (W3 @ Wlin)
    final_kernel<<<16, 256>>>((float*)d_out);
}

// round 13
// speedup vs baseline: 1.1814x; 1.1814x over previous
#include <cuda_runtime.h>
#include <cuda_fp16.h>
#include <mma.h>
#include <cstdint>

using namespace nvcuda;

#define MAX_N   100000
#define MAX_E   1600000
#define NG      256
#define DHID    64
#define NBLK_MAX 128   // ceil(MAX_N/1024) = 98 < 128

// Scratch (allocation-free rule: __device__ globals).
__device__ uint2 g_bufA[(size_t)MAX_N * 16];     // fp16 rows: m1, later h2
__device__ uint2 g_bufB[(size_t)MAX_N * 16];     // fp16 rows: relu(h1)
__device__ uint2 g_bufC[(size_t)MAX_N * 16];     // fp16 rows: agg(r1)
__device__ float g_pool[NG * DHID];
__device__ float g_cnt[NG];
__device__ float g_wc[DHID * 16];                 // W3 @ Wlin (64x16)
__device__ int   g_is64;                          // 1 if indices are int64
__device__ int   g_deg[MAX_N];                    // in-degree histogram
__device__ int   g_rowptr[MAX_N + 1];             // CSR row pointers (by dst)
__device__ int   g_wptr[MAX_N];                   // fill cursors
__device__ __align__(16) int g_col[MAX_E];        // CSR: src node per edge slot
__device__ int   g_bsum[NBLK_MAX];                // per-block partial sums

__device__ __forceinline__ int load_idx(const void* p, size_t i, int is64) {
    if (is64) return (int)(((const long long*)p)[i]);
    return ((const int*)p)[i];
}

// ---------------------------------------------------------------------------
// K1: block 0 detects index dtype (int64 values < 2^31 have zero odd words);
// other blocks zero g_deg, g_pool, g_cnt.
// ---------------------------------------------------------------------------
__global__ void init_kernel(const unsigned int* __restrict__ w, int n) {
    if (blockIdx.x == 0) {
        __shared__ unsigned int s;
        if (threadIdx.x == 0) s = 0u;
        __syncthreads();
        unsigned int v = 0u;
        for (int i = threadIdx.x; i < 1024; i += 256) v |= w[2 * i + 1];
        atomicOr(&s, v);
        __syncthreads();
        if (threadIdx.x == 0) g_is64 = (s == 0u) ? 1 : 0;
        return;
    }
    int t = (blockIdx.x - 1) * 256 + threadIdx.x;
    if (t < n) g_deg[t] = 0;
    float4 z = make_float4(0.f, 0.f, 0.f, 0.f);
    if (t < NG * 16) reinterpret_cast<float4*>(g_pool)[t] = z;
    if (t < NG / 4)  reinterpret_cast<float4*>(g_cnt)[t] = z;
}

// ---------------------------------------------------------------------------
// K2: fused small independent work: dst histogram | graph counts | Wc.
// ---------------------------------------------------------------------------
__global__ void __launch_bounds__(256) misc_kernel(
    const float* __restrict__ W3, const float* __restrict__ Wlin,
    const void* __restrict__ ei, const void* __restrict__ bat,
    int n, int E, int histB, int cntB)
{
    int b = blockIdx.x;
    if (b < histB) {
        int e = b * 256 + threadIdx.x;
        if (e < E) {
            int d = load_idx(ei, (size_t)E + e, g_is64);
            atomicAdd(&g_deg[d], 1);
        }
        return;
    }
    b -= histB;
    if (b < cntB) {
        int t = b * 256 + threadIdx.x;
        if (t < n) {
            int g = load_idx(bat, (size_t)t, g_is64);
            atomicAdd(&g_cnt[g], 1.0f);
        }
        return;
    }
    b -= cntB;
    int t = b * 256 + threadIdx.x;
    if (t < DHID * 16) {
        int i = t >> 4, o = t & 15;
        float acc = 0.f;
        #pragma unroll
        for (int k = 0; k < 64; k++)
            acc = fmaf(W3[i * 64 + k], Wlin[k * 16 + o], acc);
        g_wc[t] = acc;
    }
}

// ---------------------------------------------------------------------------
// Tensor-core matmul: out_fp16[n,64] = fp16( maybe_relu( A[n,K] @ W[K,64] ) )
// Block = 256 threads (8 warps) handles 128 rows. wmma m16n16k16, fp32 acc.
// ---------------------------------------------------------------------------
template <int K, bool A_HALF, bool RELU_OUT>
__global__ void __launch_bounds__(256) mmw_kernel(const void* __restrict__ A,
                                                  const float* __restrict__ W,
                                                  uint2* __restrict__ out,
                                                  int n) {
    __shared__ __align__(32) char raw[32768 + K * 64 * 2];
    half*  sA = reinterpret_cast<half*>(raw);
    half*  sB = reinterpret_cast<half*>(raw + 32768);
    float* sC = reinterpret_cast<float*>(raw);

    const int tid = threadIdx.x;
    const int rowbase = blockIdx.x * 128;

    const float2* W2p = reinterpret_cast<const float2*>(W);
    for (int i = tid; i < K * 32; i += 256) {
        float2 v = W2p[i];
        reinterpret_cast<half2*>(sB)[i] = __floats2half2_rn(v.x, v.y);
    }

    if (A_HALF) {
        const uint4* A4 = reinterpret_cast<const uint4*>(A);
        constexpr int RW = K / 8;
        for (int i = tid; i < 128 * RW; i += 256) {
            int r = i / RW;
            int gr = rowbase + r;
            uint4 v = make_uint4(0u, 0u, 0u, 0u);
            if (gr < n) v = A4[(size_t)gr * RW + (i % RW)];
            reinterpret_cast<uint4*>(sA)[i] = v;
        }
    } else {
        const float4* A4 = reinterpret_cast<const float4*>(A);
        constexpr int RW = K / 4;
        for (int i = tid; i < 128 * RW; i += 256) {
            int r = i / RW;
            int gr = rowbase + r;
            float4 v = make_float4(0.f, 0.f, 0.f, 0.f);
            if (gr < n) v = A4[(size_t)gr * RW + (i % RW)];
            reinterpret_cast<half2*>(sA)[i * 2]     = __floats2half2_rn(v.x, v.y);
            reinterpret_cast<half2*>(sA)[i * 2 + 1] = __floats2half2_rn(v.z, v.w);
        }
    }
    __syncthreads();

    const int w = tid >> 5;
    wmma::fragment<wmma::accumulator, 16, 16, 16, float> c[4];
    #pragma unroll
    for (int nf = 0; nf < 4; nf++) wmma::fill_fragment(c[nf], 0.f);

    #pragma unroll
    for (int k = 0; k < K / 16; k++) {
        wmma::fragment<wmma::matrix_a, 16, 16, 16, half, wmma::row_major> a;
        wmma::load_matrix_sync(a, sA + (w * 16) * K + k * 16, K);
        #pragma unroll
        for (int nf = 0; nf < 4; nf++) {
            wmma::fragment<wmma::matrix_b, 16, 16, 16, half, wmma::row_major> bfr;
            wmma::load_matrix_sync(bfr, sB + (k * 16) * 64 + nf * 16, 64);
            wmma::mma_sync(c[nf], a, bfr, c[nf]);
        }
    }
    __syncthreads();

    #pragma unroll
    for (int nf = 0; nf < 4; nf++)
        wmma::store_matrix_sync(sC + (w * 16) * 64 + nf * 16, c[nf], 64,
                                wmma::mem_row_major);
    __syncthreads();

    for (int i = tid; i < 128 * 16; i += 256) {
        int r = i >> 4, cg = i & 15;
        int gr = rowbase + r;
        if (gr >= n) continue;
        float4 v = reinterpret_cast<const float4*>(sC)[r * 16 + cg];
        if (RELU_OUT) {
            v.x = fmaxf(v.x, 0.f); v.y = fmaxf(v.y, 0.f);
            v.z = fmaxf(v.z, 0.f); v.w = fmaxf(v.w, 0.f);
        }
        __half2 p0 = __floats2half2_rn(v.x, v.y);
        __half2 p1 = __floats2half2_rn(v.z, v.w);
        out[(size_t)gr * 16 + cg] =
            make_uint2(*reinterpret_cast<unsigned*>(&p0), *reinterpret_cast<unsigned*>(&p1));
    }
}

// ---------------------------------------------------------------------------
// CSR scan stage 1: per-block sums over 1024-element chunks of g_deg.
// ---------------------------------------------------------------------------
__global__ void __launch_bounds__(256) blocksum_kernel(int n) {
    __shared__ int wsum[8];
    int tid = threadIdx.x;
    int base = blockIdx.x * 1024 + tid * 4;
    int s = 0;
    #pragma unroll
    for (int k = 0; k < 4; k++)
        if (base + k < n) s += g_deg[base + k];
    #pragma unroll
    for (int off = 16; off > 0; off >>= 1)
        s += __shfl_down_sync(0xffffffffu, s, off);
    if ((tid & 31) == 0) wsum[tid >> 5] = s;
    __syncthreads();
    if (tid == 0) {
        int t = 0;
        #pragma unroll
        for (int i = 0; i < 8; i++) t += wsum[i];
        g_bsum[blockIdx.x] = t;
    }
}

// ---------------------------------------------------------------------------
// CSR scan stage 2 (fused): block-prefix of g_bsum + local rescan -> rowptr.
// ---------------------------------------------------------------------------
__global__ void __launch_bounds__(256) writeptr_kernel(int n, int E) {
    __shared__ int tsum[256];
    __shared__ int sboff;
    int tid = threadIdx.x;

    {
        int partial = 0;
        for (int i = tid; i < blockIdx.x; i += 256) partial += g_bsum[i];
        #pragma unroll
        for (int off = 16; off > 0; off >>= 1)
            partial += __shfl_down_sync(0xffffffffu, partial, off);
        __shared__ int wsum[8];
        if ((tid & 31) == 0) wsum[tid >> 5] = partial;
        __syncthreads();
        if (tid == 0) {
            int t = 0;
            #pragma unroll
            for (int i = 0; i < 8; i++) t += wsum[i];
            sboff = t;
        }
    }

    int base = blockIdx.x * 1024 + tid * 4;
    int d[4];
    int s = 0;
    #pragma unroll
    for (int k = 0; k < 4; k++) {
        d[k] = (base + k < n) ? g_deg[base + k] : 0;
        s += d[k];
    }
    tsum[tid] = s;
    __syncthreads();
    for (int off = 1; off < 256; off <<= 1) {
        int v = (tid >= off) ? tsum[tid - off] : 0;
        __syncthreads();
        tsum[tid] += v;
        __syncthreads();
    }
    int run = ((tid > 0) ? tsum[tid - 1] : 0) + sboff;
    #pragma unroll
    for (int k = 0; k < 4; k++) {
        if (base + k < n) {
            g_rowptr[base + k] = run;
            g_wptr[base + k]   = run;
            run += d[k];
        }
    }
    if (blockIdx.x == 0 && tid == 0) g_rowptr[n] = E;
}

__global__ void __launch_bounds__(256) fill_kernel(const void* __restrict__ ei, int E) {
    int e = blockIdx.x * blockDim.x + threadIdx.x;
    if (e >= E) return;
    int is64 = g_is64;
    int s = load_idx(ei, (size_t)e, is64);
    int d = load_idx(ei, (size_t)E + e, is64);
    int pos = atomicAdd(&g_wptr[d], 1);
    g_col[pos] = s;
}

// ---------------------------------------------------------------------------
// Gather core: 16 lanes/node, uint2 per lane, int4 index loads, fp16 pairwise
// tree, fp32 accumulate. Main tier processes 8 edges (two int4 index loads,
// 8 uint2 data loads in flight) to double per-thread MLP; then 4-edge tier,
// then scalar tail.
// ---------------------------------------------------------------------------
__device__ __forceinline__ __half2 u2h(unsigned u) {
    return *reinterpret_cast<__half2*>(&u);
}

__device__ __forceinline__ void acc_u2(float4& acc, uint2 u) {
    float2 f0 = __half22float2(u2h(u.x));
    float2 f1 = __half22float2(u2h(u.y));
    acc.x += f0.x; acc.y += f0.y; acc.z += f1.x; acc.w += f1.y;
}

__device__ __forceinline__ float4 gather_core(const uint2* __restrict__ m,
                                              int node, int j) {
    int beg = g_rowptr[node];
    int end = g_rowptr[node + 1];
    float4 acc = make_float4(0.f, 0.f, 0.f, 0.f);

    int e = beg;
    int alim = (beg + 3) & ~3;
    if (alim > end) alim = end;
    for (; e < alim; e++)
        acc_u2(acc, m[(size_t)g_col[e] * 16 + j]);

    // 8-edge tier: 2 int4 index loads + 8 uint2 data loads in flight.
    for (; e + 8 <= end; e += 8) {
        int4 sa = *reinterpret_cast<const int4*>(g_col + e);
        int4 sb = *reinterpret_cast<const int4*>(g_col + e + 4);
        uint2 u0 = m[(size_t)sa.x * 16 + j];
        uint2 u1 = m[(size_t)sa.y * 16 + j];
        uint2 u2 = m[(size_t)sa.z * 16 + j];
        uint2 u3 = m[(size_t)sa.w * 16 + j];
        uint2 u4 = m[(size_t)sb.x * 16 + j];
        uint2 u5 = m[(size_t)sb.y * 16 + j];
        uint2 u6 = m[(size_t)sb.z * 16 + j];
        uint2 u7 = m[(size_t)sb.w * 16 + j];
        __half2 a0 = __hadd2(__hadd2(u2h(u0.x), u2h(u1.x)),
                             __hadd2(u2h(u2.x), u2h(u3.x)));
        __half2 b0 = __hadd2(__hadd2(u2h(u0.y), u2h(u1.y)),
                             __hadd2(u2h(u2.y), u2h(u3.y)));
        __half2 a1 = __hadd2(__hadd2(u2h(u4.x), u2h(u5.x)),
                             __hadd2(u2h(u6.x), u2h(u7.x)));
        __half2 b1 = __hadd2(__hadd2(u2h(u4.y), u2h(u5.y)),
                             __hadd2(u2h(u6.y), u2h(u7.y)));
        float2 f0 = __half22float2(a0);
        float2 f1 = __half22float2(b0);
        float2 f2 = __half22float2(a1);
        float2 f3 = __half22float2(b1);
        acc.x += f0.x + f2.x; acc.y += f0.y + f2.y;
        acc.z += f1.x + f3.x; acc.w += f1.y + f3.y;
    }
    // 4-edge tier.
    if (e + 4 <= end) {
        int4 s4 = *reinterpret_cast<const int4*>(g_col + e);
        uint2 u0 = m[(size_t)s4.x * 16 + j];
        uint2 u1 = m[(size_t)s4.y * 16 + j];
        uint2 u2 = m[(size_t)s4.z * 16 + j];
        uint2 u3 = m[(size_t)s4.w * 16 + j];
        __half2 a = __hadd2(__hadd2(u2h(u0.x), u2h(u1.x)),
                            __hadd2(u2h(u2.x), u2h(u3.x)));
        __half2 b = __hadd2(__hadd2(u2h(u0.y), u2h(u1.y)),
                            __hadd2(u2h(u2.y), u2h(u3.y)));
        float2 f0 = __half22float2(a);
        float2 f1 = __half22float2(b);
        acc.x += f0.x; acc.y += f0.y; acc.z += f1.x; acc.w += f1.y;
        e += 4;
    }
    for (; e < end; e++)
        acc_u2(acc, m[(size_t)g_col[e] * 16 + j]);
    return acc;
}

// ---------------------------------------------------------------------------
// gather_kernel<MODE>: 16 lanes/node (proven shape).
// MODE 0: out16[node] = fp16(agg)                   (layer 2 input, bufC)
// MODE 1: out16[node] = fp16(relu(agg))             (layer 1 epilogue)
// MODE 2: g_pool[batch[node]] += agg                (layer 3 + pool)
// ---------------------------------------------------------------------------
template <int MODE>
__global__ void __launch_bounds__(256) gather_kernel(const uint2* __restrict__ m,
                                                     uint2* __restrict__ out16,
                                                     int n,
                                                     const void* __restrict__ batch) {
    int t = blockIdx.x * blockDim.x + threadIdx.x;
    int node = t >> 4;
    if (node >= n) return;
    int j = t & 15;

    float4 acc = gather_core(m, node, j);

    if (MODE == 2) {
        int b = load_idx(batch, (size_t)node, g_is64);
        float* dst = g_pool + b * 64 + j * 4;
        asm volatile("red.global.add.v4.f32 [%0], {%1,%2,%3,%4};"
                     :: "l"(dst), "f"(acc.x), "f"(acc.y), "f"(acc.z), "f"(acc.w)
                     : "memory");
    } else {
        if (MODE == 1) {
            acc.x = fmaxf(acc.x, 0.f); acc.y = fmaxf(acc.y, 0.f);
            acc.z = fmaxf(acc.z, 0.f); acc.w = fmaxf(acc.w, 0.f);
        }
        __half2 p0 = __floats2half2_rn(acc.x, acc.y);
        __half2 p1 = __floats2half2_rn(acc.z, acc.w);
        out16[(size_t)node * 16 + j] =
            make_uint2(*reinterpret_cast<unsigned*>(&p0), *reinterpret_cast<unsigned*>(&p1));
    }
}

// ---------------------------------------------------------------------------
// Head: out[g,o] = (pool[g,:]/max(cnt,1)) @ Wc[:,o]   -> [256,16]
// ---------------------------------------------------------------------------
__global__ void final_kernel(float* __restrict__ out) {
    int t = blockIdx.x * blockDim.x + threadIdx.x;
    if (t >= NG * 16) return;
    int g = t >> 4, o = t & 15;
    float inv = 1.0f / fmaxf(g_cnt[g], 1.0f);
    float acc = 0.f;
    #pragma unroll
    for (int k = 0; k < 64; k++)
        acc = fmaf(g_pool[g * 64 + k], g_wc[k * 16 + o], acc);
    out[t] = acc * inv;
}

// ---------------------------------------------------------------------------
extern "C" void kernel_launch(void* const* d_in, const int* in_sizes, int n_in,
                              void* d_out, int out_size) {
    const float* x    = (const float*)d_in[0];
    const float* W1   = (const float*)d_in[1];
    const float* W2   = (const float*)d_in[2];
    const float* W3   = (const float*)d_in[3];
    const float* Wlin = (const float*)d_in[4];
    const void*  ei   = d_in[5];
    const void*  bat  = d_in[6];

    const int n = in_sizes[0] / 128;   // nodes
    const int E = in_sizes[5] / 2;     // edges

    uint2 *d_bufA, *d_bufB, *d_bufC;
    cudaGetSymbolAddress((void**)&d_bufA, g_bufA);
    cudaGetSymbolAddress((void**)&d_bufB, g_bufB);
    cudaGetSymbolAddress((void**)&d_bufC, g_bufC);

    const int mmw_blocks = (n + 127) / 128;
    const int e_blocks   = (E + 255) / 256;
    const int cnt_blocks = (n + 255) / 256;
    const int g_blocks   = (n * 16 + 255) / 256;   // 16 lanes/node
    const int nblk       = (n + 1023) / 1024;

    // K1: detect dtype + zero deg/pool/cnt.
    init_kernel<<<1 + cnt_blocks, 256>>>((const unsigned int*)ei, n);

    // mm1 on tensor cores (independent of CSR).
    mmw_kernel<128, false, false><<<mmw_blocks, 256>>>(x, W1, d_bufA, n);

    // K2: hist | count | Wc.
    misc_kernel<<<e_blocks + cnt_blocks + 4, 256>>>(
        W3, Wlin, ei, bat, n, E, e_blocks, cnt_blocks);

    // CSR scan (2 stages) + fill.
    blocksum_kernel<<<nblk, 256>>>(n);
    writeptr_kernel<<<nblk, 256>>>(n, E);
    fill_kernel<<<e_blocks, 256>>>(ei, E);

    // Layer 1: r1 = fp16(relu(agg(m1)))
    gather_kernel<1><<<g_blocks, 256>>>(d_bufA, d_bufB, n, bat);

    // Layer 2: t2 = fp16(agg(r1)); h2 = fp16(relu(t2 @ W2)) on tensor cores
    gather_kernel<0><<<g_blocks, 256>>>(d_bufB, d_bufC, n, bat);
    mmw_kernel<64, true, true><<<mmw_blocks, 256>>>(d_bufC, W2, d_bufA, n);

    // Layer 3 + pool (linearity): pool[g] += agg(h2)[node]
    gather_kernel<2><<<g_blocks, 256>>>(d_bufA, nullptr, n, bat);

    // Head: out = (pool/cnt) @ (W3 @ Wlin)
    final_kernel<<<16, 256>>>((float*)d_out);
}

// round 14
// speedup vs baseline: 1.3252x; 1.1217x over previous
#include <cuda_runtime.h>
#include <cuda_fp16.h>
#include <mma.h>
#include <cstdint>

using namespace nvcuda;

#define MAX_N   100000
#define MAX_E   1600000
#define NG      256
#define DHID    64
#define NBLK_MAX 128   // ceil(MAX_N/1024) = 98 < 128

// Scratch (allocation-free rule: __device__ globals).
__device__ uint2 g_bufA[(size_t)MAX_N * 16];     // fp16 rows: m1, later h2
__device__ uint2 g_bufB[(size_t)MAX_N * 16];     // fp16 rows: relu(h1)
__device__ uint2 g_bufC[(size_t)MAX_N * 16];     // fp16 rows: agg(r1)
__device__ float g_pool[NG * DHID];
__device__ float g_cnt[NG];
__device__ float g_wc[DHID * 16];                 // W3 @ Wlin (64x16)
__device__ int   g_is64;                          // 1 if indices are int64
__device__ int   g_deg[MAX_N];                    // in-degree histogram
__device__ int   g_rowptr[MAX_N + 1];             // CSR row pointers (by dst)
__device__ int   g_wptr[MAX_N];                   // fill cursors
__device__ __align__(16) int g_col[MAX_E];        // CSR: src node per edge slot
__device__ int   g_bsum[NBLK_MAX];                // per-block partial sums

// Side stream + fork/join events, created once at static-init time (host
// resources only; no device-memory allocation APIs involved).
struct SideStream {
    cudaStream_t s;
    cudaEvent_t fork, join;
    SideStream() {
        cudaStreamCreateWithFlags(&s, cudaStreamNonBlocking);
        cudaEventCreateWithFlags(&fork, cudaEventDisableTiming);
        cudaEventCreateWithFlags(&join, cudaEventDisableTiming);
    }
};
static SideStream g_side;

__device__ __forceinline__ int load_idx(const void* p, size_t i, int is64) {
    if (is64) return (int)(((const long long*)p)[i]);
    return ((const int*)p)[i];
}

// ---------------------------------------------------------------------------
// K1: block 0 detects index dtype (int64 values < 2^31 have zero odd words);
// other blocks zero g_deg, g_pool, g_cnt.
// ---------------------------------------------------------------------------
__global__ void init_kernel(const unsigned int* __restrict__ w, int n) {
    if (blockIdx.x == 0) {
        __shared__ unsigned int s;
        if (threadIdx.x == 0) s = 0u;
        __syncthreads();
        unsigned int v = 0u;
        for (int i = threadIdx.x; i < 1024; i += 256) v |= w[2 * i + 1];
        atomicOr(&s, v);
        __syncthreads();
        if (threadIdx.x == 0) g_is64 = (s == 0u) ? 1 : 0;
        return;
    }
    int t = (blockIdx.x - 1) * 256 + threadIdx.x;
    if (t < n) g_deg[t] = 0;
    float4 z = make_float4(0.f, 0.f, 0.f, 0.f);
    if (t < NG * 16) reinterpret_cast<float4*>(g_pool)[t] = z;
    if (t < NG / 4)  reinterpret_cast<float4*>(g_cnt)[t] = z;
}

// ---------------------------------------------------------------------------
// K2: fused small independent work: dst histogram | graph counts | Wc.
// ---------------------------------------------------------------------------
__global__ void __launch_bounds__(256) misc_kernel(
    const float* __restrict__ W3, const float* __restrict__ Wlin,
    const void* __restrict__ ei, const void* __restrict__ bat,
    int n, int E, int histB, int cntB)
{
    int b = blockIdx.x;
    if (b < histB) {
        int e = b * 256 + threadIdx.x;
        if (e < E) {
            int d = load_idx(ei, (size_t)E + e, g_is64);
            atomicAdd(&g_deg[d], 1);
        }
        return;
    }
    b -= histB;
    if (b < cntB) {
        int t = b * 256 + threadIdx.x;
        if (t < n) {
            int g = load_idx(bat, (size_t)t, g_is64);
            atomicAdd(&g_cnt[g], 1.0f);
        }
        return;
    }
    b -= cntB;
    int t = b * 256 + threadIdx.x;
    if (t < DHID * 16) {
        int i = t >> 4, o = t & 15;
        float acc = 0.f;
        #pragma unroll
        for (int k = 0; k < 64; k++)
            acc = fmaf(W3[i * 64 + k], Wlin[k * 16 + o], acc);
        g_wc[t] = acc;
    }
}

// ---------------------------------------------------------------------------
// Tensor-core matmul: out_fp16[n,64] = fp16( maybe_relu( A[n,K] @ W[K,64] ) )
// Block = 256 threads (8 warps) handles 128 rows. wmma m16n16k16, fp32 acc.
// ---------------------------------------------------------------------------
template <int K, bool A_HALF, bool RELU_OUT>
__global__ void __launch_bounds__(256) mmw_kernel(const void* __restrict__ A,
                                                  const float* __restrict__ W,
                                                  uint2* __restrict__ out,
                                                  int n) {
    __shared__ __align__(32) char raw[32768 + K * 64 * 2];
    half*  sA = reinterpret_cast<half*>(raw);
    half*  sB = reinterpret_cast<half*>(raw + 32768);
    float* sC = reinterpret_cast<float*>(raw);

    const int tid = threadIdx.x;
    const int rowbase = blockIdx.x * 128;

    const float2* W2p = reinterpret_cast<const float2*>(W);
    for (int i = tid; i < K * 32; i += 256) {
        float2 v = W2p[i];
        reinterpret_cast<half2*>(sB)[i] = __floats2half2_rn(v.x, v.y);
    }

    if (A_HALF) {
        const uint4* A4 = reinterpret_cast<const uint4*>(A);
        constexpr int RW = K / 8;
        for (int i = tid; i < 128 * RW; i += 256) {
            int r = i / RW;
            int gr = rowbase + r;
            uint4 v = make_uint4(0u, 0u, 0u, 0u);
            if (gr < n) v = A4[(size_t)gr * RW + (i % RW)];
            reinterpret_cast<uint4*>(sA)[i] = v;
        }
    } else {
        const float4* A4 = reinterpret_cast<const float4*>(A);
        constexpr int RW = K / 4;
        for (int i = tid; i < 128 * RW; i += 256) {
            int r = i / RW;
            int gr = rowbase + r;
            float4 v = make_float4(0.f, 0.f, 0.f, 0.f);
            if (gr < n) v = A4[(size_t)gr * RW + (i % RW)];
            reinterpret_cast<half2*>(sA)[i * 2]     = __floats2half2_rn(v.x, v.y);
            reinterpret_cast<half2*>(sA)[i * 2 + 1] = __floats2half2_rn(v.z, v.w);
        }
    }
    __syncthreads();

    const int w = tid >> 5;
    wmma::fragment<wmma::accumulator, 16, 16, 16, float> c[4];
    #pragma unroll
    for (int nf = 0; nf < 4; nf++) wmma::fill_fragment(c[nf], 0.f);

    #pragma unroll
    for (int k = 0; k < K / 16; k++) {
        wmma::fragment<wmma::matrix_a, 16, 16, 16, half, wmma::row_major> a;
        wmma::load_matrix_sync(a, sA + (w * 16) * K + k * 16, K);
        #pragma unroll
        for (int nf = 0; nf < 4; nf++) {
            wmma::fragment<wmma::matrix_b, 16, 16, 16, half, wmma::row_major> bfr;
            wmma::load_matrix_sync(bfr, sB + (k * 16) * 64 + nf * 16, 64);
            wmma::mma_sync(c[nf], a, bfr, c[nf]);
        }
    }
    __syncthreads();

    #pragma unroll
    for (int nf = 0; nf < 4; nf++)
        wmma::store_matrix_sync(sC + (w * 16) * 64 + nf * 16, c[nf], 64,
                                wmma::mem_row_major);
    __syncthreads();

    for (int i = tid; i < 128 * 16; i += 256) {
        int r = i >> 4, cg = i & 15;
        int gr = rowbase + r;
        if (gr >= n) continue;
        float4 v = reinterpret_cast<const float4*>(sC)[r * 16 + cg];
        if (RELU_OUT) {
            v.x = fmaxf(v.x, 0.f); v.y = fmaxf(v.y, 0.f);
            v.z = fmaxf(v.z, 0.f); v.w = fmaxf(v.w, 0.f);
        }
        __half2 p0 = __floats2half2_rn(v.x, v.y);
        __half2 p1 = __floats2half2_rn(v.z, v.w);
        out[(size_t)gr * 16 + cg] =
            make_uint2(*reinterpret_cast<unsigned*>(&p0), *reinterpret_cast<unsigned*>(&p1));
    }
}

// ---------------------------------------------------------------------------
// CSR scan stage 1: per-block sums over 1024-element chunks of g_deg.
// ---------------------------------------------------------------------------
__global__ void __launch_bounds__(256) blocksum_kernel(int n) {
    __shared__ int wsum[8];
    int tid = threadIdx.x;
    int base = blockIdx.x * 1024 + tid * 4;
    int s = 0;
    #pragma unroll
    for (int k = 0; k < 4; k++)
        if (base + k < n) s += g_deg[base + k];
    #pragma unroll
    for (int off = 16; off > 0; off >>= 1)
        s += __shfl_down_sync(0xffffffffu, s, off);
    if ((tid & 31) == 0) wsum[tid >> 5] = s;
    __syncthreads();
    if (tid == 0) {
        int t = 0;
        #pragma unroll
        for (int i = 0; i < 8; i++) t += wsum[i];
        g_bsum[blockIdx.x] = t;
    }
}

// ---------------------------------------------------------------------------
// CSR scan stage 2 (fused): block-prefix of g_bsum + local rescan -> rowptr.
// ---------------------------------------------------------------------------
__global__ void __launch_bounds__(256) writeptr_kernel(int n, int E) {
    __shared__ int tsum[256];
    __shared__ int sboff;
    int tid = threadIdx.x;

    {
        int partial = 0;
        for (int i = tid; i < blockIdx.x; i += 256) partial += g_bsum[i];
        #pragma unroll
        for (int off = 16; off > 0; off >>= 1)
            partial += __shfl_down_sync(0xffffffffu, partial, off);
        __shared__ int wsum[8];
        if ((tid & 31) == 0) wsum[tid >> 5] = partial;
        __syncthreads();
        if (tid == 0) {
            int t = 0;
            #pragma unroll
            for (int i = 0; i < 8; i++) t += wsum[i];
            sboff = t;
        }
    }

    int base = blockIdx.x * 1024 + tid * 4;
    int d[4];
    int s = 0;
    #pragma unroll
    for (int k = 0; k < 4; k++) {
        d[k] = (base + k < n) ? g_deg[base + k] : 0;
        s += d[k];
    }
    tsum[tid] = s;
    __syncthreads();
    for (int off = 1; off < 256; off <<= 1) {
        int v = (tid >= off) ? tsum[tid - off] : 0;
        __syncthreads();
        tsum[tid] += v;
        __syncthreads();
    }
    int run = ((tid > 0) ? tsum[tid - 1] : 0) + sboff;
    #pragma unroll
    for (int k = 0; k < 4; k++) {
        if (base + k < n) {
            g_rowptr[base + k] = run;
            g_wptr[base + k]   = run;
            run += d[k];
        }
    }
    if (blockIdx.x == 0 && tid == 0) g_rowptr[n] = E;
}

__global__ void __launch_bounds__(256) fill_kernel(const void* __restrict__ ei, int E) {
    int e = blockIdx.x * blockDim.x + threadIdx.x;
    if (e >= E) return;
    int is64 = g_is64;
    int s = load_idx(ei, (size_t)e, is64);
    int d = load_idx(ei, (size_t)E + e, is64);
    int pos = atomicAdd(&g_wptr[d], 1);
    g_col[pos] = s;
}

// ---------------------------------------------------------------------------
// Gather core: 16 lanes/node, uint2 per lane, int4 index loads, fp16 pairwise
// tree, fp32 accumulate. 8-edge main tier, 4-edge tier, scalar tail.
// ---------------------------------------------------------------------------
__device__ __forceinline__ __half2 u2h(unsigned u) {
    return *reinterpret_cast<__half2*>(&u);
}

__device__ __forceinline__ void acc_u2(float4& acc, uint2 u) {
    float2 f0 = __half22float2(u2h(u.x));
    float2 f1 = __half22float2(u2h(u.y));
    acc.x += f0.x; acc.y += f0.y; acc.z += f1.x; acc.w += f1.y;
}

__device__ __forceinline__ float4 gather_core(const uint2* __restrict__ m,
                                              int node, int j) {
    int beg = g_rowptr[node];
    int end = g_rowptr[node + 1];
    float4 acc = make_float4(0.f, 0.f, 0.f, 0.f);

    int e = beg;
    int alim = (beg + 3) & ~3;
    if (alim > end) alim = end;
    for (; e < alim; e++)
        acc_u2(acc, m[(size_t)g_col[e] * 16 + j]);

    for (; e + 8 <= end; e += 8) {
        int4 sa = *reinterpret_cast<const int4*>(g_col + e);
        int4 sb = *reinterpret_cast<const int4*>(g_col + e + 4);
        uint2 u0 = m[(size_t)sa.x * 16 + j];
        uint2 u1 = m[(size_t)sa.y * 16 + j];
        uint2 u2 = m[(size_t)sa.z * 16 + j];
        uint2 u3 = m[(size_t)sa.w * 16 + j];
        uint2 u4 = m[(size_t)sb.x * 16 + j];
        uint2 u5 = m[(size_t)sb.y * 16 + j];
        uint2 u6 = m[(size_t)sb.z * 16 + j];
        uint2 u7 = m[(size_t)sb.w * 16 + j];
        __half2 a0 = __hadd2(__hadd2(u2h(u0.x), u2h(u1.x)),
                             __hadd2(u2h(u2.x), u2h(u3.x)));
        __half2 b0 = __hadd2(__hadd2(u2h(u0.y), u2h(u1.y)),
                             __hadd2(u2h(u2.y), u2h(u3.y)));
        __half2 a1 = __hadd2(__hadd2(u2h(u4.x), u2h(u5.x)),
                             __hadd2(u2h(u6.x), u2h(u7.x)));
        __half2 b1 = __hadd2(__hadd2(u2h(u4.y), u2h(u5.y)),
                             __hadd2(u2h(u6.y), u2h(u7.y)));
        float2 f0 = __half22float2(a0);
        float2 f1 = __half22float2(b0);
        float2 f2 = __half22float2(a1);
        float2 f3 = __half22float2(b1);
        acc.x += f0.x + f2.x; acc.y += f0.y + f2.y;
        acc.z += f1.x + f3.x; acc.w += f1.y + f3.y;
    }
    if (e + 4 <= end) {
        int4 s4 = *reinterpret_cast<const int4*>(g_col + e);
        uint2 u0 = m[(size_t)s4.x * 16 + j];
        uint2 u1 = m[(size_t)s4.y * 16 + j];
        uint2 u2 = m[(size_t)s4.z * 16 + j];
        uint2 u3 = m[(size_t)s4.w * 16 + j];
        __half2 a = __hadd2(__hadd2(u2h(u0.x), u2h(u1.x)),
                            __hadd2(u2h(u2.x), u2h(u3.x)));
        __half2 b = __hadd2(__hadd2(u2h(u0.y), u2h(u1.y)),
                            __hadd2(u2h(u2.y), u2h(u3.y)));
        float2 f0 = __half22float2(a);
        float2 f1 = __half22float2(b);
        acc.x += f0.x; acc.y += f0.y; acc.z += f1.x; acc.w += f1.y;
        e += 4;
    }
    for (; e < end; e++)
        acc_u2(acc, m[(size_t)g_col[e] * 16 + j]);
    return acc;
}

// ---------------------------------------------------------------------------
// gather_kernel<MODE>: 16 lanes/node (proven shape).
// MODE 0: out16[node] = fp16(agg)                   (layer 2 input, bufC)
// MODE 1: out16[node] = fp16(relu(agg))             (layer 1 epilogue)
// MODE 2: g_pool[batch[node]] += agg                (layer 3 + pool)
// ---------------------------------------------------------------------------
template <int MODE>
__global__ void __launch_bounds__(256) gather_kernel(const uint2* __restrict__ m,
                                                     uint2* __restrict__ out16,
                                                     int n,
                                                     const void* __restrict__ batch) {
    int t = blockIdx.x * blockDim.x + threadIdx.x;
    int node = t >> 4;
    if (node >= n) return;
    int j = t & 15;

    float4 acc = gather_core(m, node, j);

    if (MODE == 2) {
        int b = load_idx(batch, (size_t)node, g_is64);
        float* dst = g_pool + b * 64 + j * 4;
        asm volatile("red.global.add.v4.f32 [%0], {%1,%2,%3,%4};"
                     :: "l"(dst), "f"(acc.x), "f"(acc.y), "f"(acc.z), "f"(acc.w)
                     : "memory");
    } else {
        if (MODE == 1) {
            acc.x = fmaxf(acc.x, 0.f); acc.y = fmaxf(acc.y, 0.f);
            acc.z = fmaxf(acc.z, 0.f); acc.w = fmaxf(acc.w, 0.f);
        }
        __half2 p0 = __floats2half2_rn(acc.x, acc.y);
        __half2 p1 = __floats2half2_rn(acc.z, acc.w);
        out16[(size_t)node * 16 + j] =
            make_uint2(*reinterpret_cast<unsigned*>(&p0), *reinterpret_cast<unsigned*>(&p1));
    }
}

// ---------------------------------------------------------------------------
// Head: out[g,o] = (pool[g,:]/max(cnt,1)) @ Wc[:,o]   -> [256,16]
// ---------------------------------------------------------------------------
__global__ void final_kernel(float* __restrict__ out) {
    int t = blockIdx.x * blockDim.x + threadIdx.x;
    if (t >= NG * 16) return;
    int g = t >> 4, o = t & 15;
    float inv = 1.0f / fmaxf(g_cnt[g], 1.0f);
    float acc = 0.f;
    #pragma unroll
    for (int k = 0; k < 64; k++)
        acc = fmaf(g_pool[g * 64 + k], g_wc[k * 16 + o], acc);
    out[t] = acc * inv;
}

// ---------------------------------------------------------------------------
extern "C" void kernel_launch(void* const* d_in, const int* in_sizes, int n_in,
                              void* d_out, int out_size) {
    const float* x    = (const float*)d_in[0];
    const float* W1   = (const float*)d_in[1];
    const float* W2   = (const float*)d_in[2];
    const float* W3   = (const float*)d_in[3];
    const float* Wlin = (const float*)d_in[4];
    const void*  ei   = d_in[5];
    const void*  bat  = d_in[6];

    const int n = in_sizes[0] / 128;   // nodes
    const int E = in_sizes[5] / 2;     // edges

    uint2 *d_bufA, *d_bufB, *d_bufC;
    cudaGetSymbolAddress((void**)&d_bufA, g_bufA);
    cudaGetSymbolAddress((void**)&d_bufB, g_bufB);
    cudaGetSymbolAddress((void**)&d_bufC, g_bufC);

    const int mmw_blocks = (n + 127) / 128;
    const int e_blocks   = (E + 255) / 256;
    const int cnt_blocks = (n + 255) / 256;
    const int g_blocks   = (n * 16 + 255) / 256;   // 16 lanes/node
    const int nblk       = (n + 1023) / 1024;

    // Fork: mm1 (independent of CSR build) runs on a parallel graph branch.
    cudaEventRecord(g_side.fork, 0);
    cudaStreamWaitEvent(g_side.s, g_side.fork, 0);
    mmw_kernel<128, false, false><<<mmw_blocks, 256, 0, g_side.s>>>(x, W1, d_bufA, n);
    cudaEventRecord(g_side.join, g_side.s);

    // Main branch: CSR build chain.
    init_kernel<<<1 + cnt_blocks, 256>>>((const unsigned int*)ei, n);
    misc_kernel<<<e_blocks + cnt_blocks + 4, 256>>>(
        W3, Wlin, ei, bat, n, E, e_blocks, cnt_blocks);
    blocksum_kernel<<<nblk, 256>>>(n);
    writeptr_kernel<<<nblk, 256>>>(n, E);
    fill_kernel<<<e_blocks, 256>>>(ei, E);

    // Join: gather1 needs both CSR (main) and m1 (side).
    cudaStreamWaitEvent(0, g_side.join, 0);

    // Layer 1: r1 = fp16(relu(agg(m1)))
    gather_kernel<1><<<g_blocks, 256>>>(d_bufA, d_bufB, n, bat);

    // Layer 2: t2 = fp16(agg(r1)); h2 = fp16(relu(t2 @ W2)) on tensor cores
    gather_kernel<0><<<g_blocks, 256>>>(d_bufB, d_bufC, n, bat);
    mmw_kernel<64, true, true><<<mmw_blocks, 256>>>(d_bufC, W2, d_bufA, n);

    // Layer 3 + pool (linearity): pool[g] += agg(h2)[node]
    gather_kernel<2><<<g_blocks, 256>>>(d_bufA, nullptr, n, bat);

    // Head: out = (pool/cnt) @ (W3 @ Wlin)
    final_kernel<<<16, 256>>>((float*)d_out);
}

// round 15
// speedup vs baseline: 1.3390x; 1.0104x over previous
#include <cuda_runtime.h>
#include <cuda_fp16.h>
#include <mma.h>
#include <cstdint>

using namespace nvcuda;

#define MAX_N   100000
#define MAX_E   1600000
#define NG      256
#define DHID    64
#define NBLK_MAX 128   // ceil(MAX_N/1024) = 98 < 128

// Scratch (allocation-free rule: __device__ globals).
__device__ uint2 g_bufA[(size_t)MAX_N * 16];     // fp16 rows: m1, later h2
__device__ uint2 g_bufB[(size_t)MAX_N * 16];     // fp16 rows: relu(h1)
__device__ uint2 g_bufC[(size_t)MAX_N * 16];     // fp16 rows: agg(r1)
__device__ float g_pool[NG * DHID];
__device__ float g_cnt[NG];
__device__ float g_wc[DHID * 16];                 // W3 @ Wlin (64x16)
__device__ int   g_is64;                          // 1 if indices are int64
__device__ int   g_deg[MAX_N];                    // in-degree histogram
__device__ int   g_rowptr[MAX_N + 1];             // CSR row pointers (by dst)
__device__ int   g_wptr[MAX_N];                   // fill cursors
__device__ __align__(16) int g_col[MAX_E];        // CSR: src node per edge slot
__device__ int   g_bsum[NBLK_MAX];                // per-block partial sums

// Side stream + fork/join events, created once at static-init time (host
// resources only; no device-memory allocation APIs involved).
struct SideStream {
    cudaStream_t s;
    cudaEvent_t fork, join_mm1, join_misc;
    SideStream() {
        cudaStreamCreateWithFlags(&s, cudaStreamNonBlocking);
        cudaEventCreateWithFlags(&fork, cudaEventDisableTiming);
        cudaEventCreateWithFlags(&join_mm1, cudaEventDisableTiming);
        cudaEventCreateWithFlags(&join_misc, cudaEventDisableTiming);
    }
};
static SideStream g_side;

__device__ __forceinline__ int load_idx(const void* p, size_t i, int is64) {
    if (is64) return (int)(((const long long*)p)[i]);
    return ((const int*)p)[i];
}

// ---------------------------------------------------------------------------
// K1: block 0 detects index dtype (int64 values < 2^31 have zero odd words);
// other blocks zero g_deg, g_pool, g_cnt.
// ---------------------------------------------------------------------------
__global__ void init_kernel(const unsigned int* __restrict__ w, int n) {
    if (blockIdx.x == 0) {
        __shared__ unsigned int s;
        if (threadIdx.x == 0) s = 0u;
        __syncthreads();
        unsigned int v = 0u;
        for (int i = threadIdx.x; i < 1024; i += 256) v |= w[2 * i + 1];
        atomicOr(&s, v);
        __syncthreads();
        if (threadIdx.x == 0) g_is64 = (s == 0u) ? 1 : 0;
        return;
    }
    int t = (blockIdx.x - 1) * 256 + threadIdx.x;
    if (t < n) g_deg[t] = 0;
    float4 z = make_float4(0.f, 0.f, 0.f, 0.f);
    if (t < NG * 16) reinterpret_cast<float4*>(g_pool)[t] = z;
    if (t < NG / 4)  reinterpret_cast<float4*>(g_cnt)[t] = z;
}

// ---------------------------------------------------------------------------
// Dedicated dst histogram (critical path): 4 edges/thread.
// ---------------------------------------------------------------------------
__global__ void __launch_bounds__(256) hist_kernel(const void* __restrict__ ei, int E) {
    int base = (blockIdx.x * 256 + threadIdx.x) * 4;
    if (base >= E) return;
    int is64 = g_is64;
    #pragma unroll
    for (int k = 0; k < 4; k++) {
        int e = base + k;
        if (e < E) atomicAdd(&g_deg[load_idx(ei, (size_t)E + e, is64)], 1);
    }
}

// ---------------------------------------------------------------------------
// Side-stream misc: per-graph node counts | Wc = W3 @ Wlin. Off critical path.
// ---------------------------------------------------------------------------
__global__ void __launch_bounds__(256) side_misc_kernel(
    const float* __restrict__ W3, const float* __restrict__ Wlin,
    const void* __restrict__ bat, int n, int cntB)
{
    int b = blockIdx.x;
    if (b < cntB) {
        int t = b * 256 + threadIdx.x;
        if (t < n) {
            int g = load_idx(bat, (size_t)t, g_is64);
            atomicAdd(&g_cnt[g], 1.0f);
        }
        return;
    }
    b -= cntB;
    int t = b * 256 + threadIdx.x;
    if (t < DHID * 16) {
        int i = t >> 4, o = t & 15;
        float acc = 0.f;
        #pragma unroll
        for (int k = 0; k < 64; k++)
            acc = fmaf(W3[i * 64 + k], Wlin[k * 16 + o], acc);
        g_wc[t] = acc;
    }
}

// ---------------------------------------------------------------------------
// Tensor-core matmul: out_fp16[n,64] = fp16( maybe_relu( A[n,K] @ W[K,64] ) )
// Block = 256 threads (8 warps) handles 128 rows. wmma m16n16k16, fp32 acc.
// ---------------------------------------------------------------------------
template <int K, bool A_HALF, bool RELU_OUT>
__global__ void __launch_bounds__(256) mmw_kernel(const void* __restrict__ A,
                                                  const float* __restrict__ W,
                                                  uint2* __restrict__ out,
                                                  int n) {
    __shared__ __align__(32) char raw[32768 + K * 64 * 2];
    half*  sA = reinterpret_cast<half*>(raw);
    half*  sB = reinterpret_cast<half*>(raw + 32768);
    float* sC = reinterpret_cast<float*>(raw);

    const int tid = threadIdx.x;
    const int rowbase = blockIdx.x * 128;

    const float2* W2p = reinterpret_cast<const float2*>(W);
    for (int i = tid; i < K * 32; i += 256) {
        float2 v = W2p[i];
        reinterpret_cast<half2*>(sB)[i] = __floats2half2_rn(v.x, v.y);
    }

    if (A_HALF) {
        const uint4* A4 = reinterpret_cast<const uint4*>(A);
        constexpr int RW = K / 8;
        for (int i = tid; i < 128 * RW; i += 256) {
            int r = i / RW;
            int gr = rowbase + r;
            uint4 v = make_uint4(0u, 0u, 0u, 0u);
            if (gr < n) v = A4[(size_t)gr * RW + (i % RW)];
            reinterpret_cast<uint4*>(sA)[i] = v;
        }
    } else {
        const float4* A4 = reinterpret_cast<const float4*>(A);
        constexpr int RW = K / 4;
        for (int i = tid; i < 128 * RW; i += 256) {
            int r = i / RW;
            int gr = rowbase + r;
            float4 v = make_float4(0.f, 0.f, 0.f, 0.f);
            if (gr < n) v = A4[(size_t)gr * RW + (i % RW)];
            reinterpret_cast<half2*>(sA)[i * 2]     = __floats2half2_rn(v.x, v.y);
            reinterpret_cast<half2*>(sA)[i * 2 + 1] = __floats2half2_rn(v.z, v.w);
        }
    }
    __syncthreads();

    const int w = tid >> 5;
    wmma::fragment<wmma::accumulator, 16, 16, 16, float> c[4];
    #pragma unroll
    for (int nf = 0; nf < 4; nf++) wmma::fill_fragment(c[nf], 0.f);

    #pragma unroll
    for (int k = 0; k < K / 16; k++) {
        wmma::fragment<wmma::matrix_a, 16, 16, 16, half, wmma::row_major> a;
        wmma::load_matrix_sync(a, sA + (w * 16) * K + k * 16, K);
        #pragma unroll
        for (int nf = 0; nf < 4; nf++) {
            wmma::fragment<wmma::matrix_b, 16, 16, 16, half, wmma::row_major> bfr;
            wmma::load_matrix_sync(bfr, sB + (k * 16) * 64 + nf * 16, 64);
            wmma::mma_sync(c[nf], a, bfr, c[nf]);
        }
    }
    __syncthreads();

    #pragma unroll
    for (int nf = 0; nf < 4; nf++)
        wmma::store_matrix_sync(sC + (w * 16) * 64 + nf * 16, c[nf], 64,
                                wmma::mem_row_major);
    __syncthreads();

    for (int i = tid; i < 128 * 16; i += 256) {
        int r = i >> 4, cg = i & 15;
        int gr = rowbase + r;
        if (gr >= n) continue;
        float4 v = reinterpret_cast<const float4*>(sC)[r * 16 + cg];
        if (RELU_OUT) {
            v.x = fmaxf(v.x, 0.f); v.y = fmaxf(v.y, 0.f);
            v.z = fmaxf(v.z, 0.f); v.w = fmaxf(v.w, 0.f);
        }
        __half2 p0 = __floats2half2_rn(v.x, v.y);
        __half2 p1 = __floats2half2_rn(v.z, v.w);
        out[(size_t)gr * 16 + cg] =
            make_uint2(*reinterpret_cast<unsigned*>(&p0), *reinterpret_cast<unsigned*>(&p1));
    }
}

// ---------------------------------------------------------------------------
// CSR scan stage 1: per-block sums over 1024-element chunks of g_deg.
// ---------------------------------------------------------------------------
__global__ void __launch_bounds__(256) blocksum_kernel(int n) {
    __shared__ int wsum[8];
    int tid = threadIdx.x;
    int base = blockIdx.x * 1024 + tid * 4;
    int s = 0;
    #pragma unroll
    for (int k = 0; k < 4; k++)
        if (base + k < n) s += g_deg[base + k];
    #pragma unroll
    for (int off = 16; off > 0; off >>= 1)
        s += __shfl_down_sync(0xffffffffu, s, off);
    if ((tid & 31) == 0) wsum[tid >> 5] = s;
    __syncthreads();
    if (tid == 0) {
        int t = 0;
        #pragma unroll
        for (int i = 0; i < 8; i++) t += wsum[i];
        g_bsum[blockIdx.x] = t;
    }
}

// ---------------------------------------------------------------------------
// CSR scan stage 2 (fused): block-prefix of g_bsum + local rescan -> rowptr.
// ---------------------------------------------------------------------------
__global__ void __launch_bounds__(256) writeptr_kernel(int n, int E) {
    __shared__ int tsum[256];
    __shared__ int sboff;
    int tid = threadIdx.x;

    {
        int partial = 0;
        for (int i = tid; i < blockIdx.x; i += 256) partial += g_bsum[i];
        #pragma unroll
        for (int off = 16; off > 0; off >>= 1)
            partial += __shfl_down_sync(0xffffffffu, partial, off);
        __shared__ int wsum[8];
        if ((tid & 31) == 0) wsum[tid >> 5] = partial;
        __syncthreads();
        if (tid == 0) {
            int t = 0;
            #pragma unroll
            for (int i = 0; i < 8; i++) t += wsum[i];
            sboff = t;
        }
    }

    int base = blockIdx.x * 1024 + tid * 4;
    int d[4];
    int s = 0;
    #pragma unroll
    for (int k = 0; k < 4; k++) {
        d[k] = (base + k < n) ? g_deg[base + k] : 0;
        s += d[k];
    }
    tsum[tid] = s;
    __syncthreads();
    for (int off = 1; off < 256; off <<= 1) {
        int v = (tid >= off) ? tsum[tid - off] : 0;
        __syncthreads();
        tsum[tid] += v;
        __syncthreads();
    }
    int run = ((tid > 0) ? tsum[tid - 1] : 0) + sboff;
    #pragma unroll
    for (int k = 0; k < 4; k++) {
        if (base + k < n) {
            g_rowptr[base + k] = run;
            g_wptr[base + k]   = run;
            run += d[k];
        }
    }
    if (blockIdx.x == 0 && tid == 0) g_rowptr[n] = E;
}

__global__ void __launch_bounds__(256) fill_kernel(const void* __restrict__ ei, int E) {
    int e = blockIdx.x * blockDim.x + threadIdx.x;
    if (e >= E) return;
    int is64 = g_is64;
    int s = load_idx(ei, (size_t)e, is64);
    int d = load_idx(ei, (size_t)E + e, is64);
    int pos = atomicAdd(&g_wptr[d], 1);
    g_col[pos] = s;
}

// ---------------------------------------------------------------------------
// Gather core: 16 lanes/node, uint2 per lane, int4 index loads, fp16 pairwise
// tree, fp32 accumulate. 8-edge main tier, 4-edge tier, scalar tail.
// ---------------------------------------------------------------------------
__device__ __forceinline__ __half2 u2h(unsigned u) {
    return *reinterpret_cast<__half2*>(&u);
}

__device__ __forceinline__ void acc_u2(float4& acc, uint2 u) {
    float2 f0 = __half22float2(u2h(u.x));
    float2 f1 = __half22float2(u2h(u.y));
    acc.x += f0.x; acc.y += f0.y; acc.z += f1.x; acc.w += f1.y;
}

__device__ __forceinline__ float4 gather_core(const uint2* __restrict__ m,
                                              int node, int j) {
    int beg = g_rowptr[node];
    int end = g_rowptr[node + 1];
    float4 acc = make_float4(0.f, 0.f, 0.f, 0.f);

    int e = beg;
    int alim = (beg + 3) & ~3;
    if (alim > end) alim = end;
    for (; e < alim; e++)
        acc_u2(acc, m[(size_t)g_col[e] * 16 + j]);

    for (; e + 8 <= end; e += 8) {
        int4 sa = *reinterpret_cast<const int4*>(g_col + e);
        int4 sb = *reinterpret_cast<const int4*>(g_col + e + 4);
        uint2 u0 = m[(size_t)sa.x * 16 + j];
        uint2 u1 = m[(size_t)sa.y * 16 + j];
        uint2 u2 = m[(size_t)sa.z * 16 + j];
        uint2 u3 = m[(size_t)sa.w * 16 + j];
        uint2 u4 = m[(size_t)sb.x * 16 + j];
        uint2 u5 = m[(size_t)sb.y * 16 + j];
        uint2 u6 = m[(size_t)sb.z * 16 + j];
        uint2 u7 = m[(size_t)sb.w * 16 + j];
        __half2 a0 = __hadd2(__hadd2(u2h(u0.x), u2h(u1.x)),
                             __hadd2(u2h(u2.x), u2h(u3.x)));
        __half2 b0 = __hadd2(__hadd2(u2h(u0.y), u2h(u1.y)),
                             __hadd2(u2h(u2.y), u2h(u3.y)));
        __half2 a1 = __hadd2(__hadd2(u2h(u4.x), u2h(u5.x)),
                             __hadd2(u2h(u6.x), u2h(u7.x)));
        __half2 b1 = __hadd2(__hadd2(u2h(u4.y), u2h(u5.y)),
                             __hadd2(u2h(u6.y), u2h(u7.y)));
        float2 f0 = __half22float2(a0);
        float2 f1 = __half22float2(b0);
        float2 f2 = __half22float2(a1);
        float2 f3 = __half22float2(b1);
        acc.x += f0.x + f2.x; acc.y += f0.y + f2.y;
        acc.z += f1.x + f3.x; acc.w += f1.y + f3.y;
    }
    if (e + 4 <= end) {
        int4 s4 = *reinterpret_cast<const int4*>(g_col + e);
        uint2 u0 = m[(size_t)s4.x * 16 + j];
        uint2 u1 = m[(size_t)s4.y * 16 + j];
        uint2 u2 = m[(size_t)s4.z * 16 + j];
        uint2 u3 = m[(size_t)s4.w * 16 + j];
        __half2 a = __hadd2(__hadd2(u2h(u0.x), u2h(u1.x)),
                            __hadd2(u2h(u2.x), u2h(u3.x)));
        __half2 b = __hadd2(__hadd2(u2h(u0.y), u2h(u1.y)),
                            __hadd2(u2h(u2.y), u2h(u3.y)));
        float2 f0 = __half22float2(a);
        float2 f1 = __half22float2(b);
        acc.x += f0.x; acc.y += f0.y; acc.z += f1.x; acc.w += f1.y;
        e += 4;
    }
    for (; e < end; e++)
        acc_u2(acc, m[(size_t)g_col[e] * 16 + j]);
    return acc;
}

// ---------------------------------------------------------------------------
// gather_kernel<MODE>: 16 lanes/node (proven shape).
// MODE 0: out16[node] = fp16(agg)                   (layer 2 input, bufC)
// MODE 1: out16[node] = fp16(relu(agg))             (layer 1 epilogue)
// MODE 2: g_pool[batch[node]] += agg                (layer 3 + pool)
// ---------------------------------------------------------------------------
template <int MODE>
__global__ void __launch_bounds__(256) gather_kernel(const uint2* __restrict__ m,
                                                     uint2* __restrict__ out16,
                                                     int n,
                                                     const void* __restrict__ batch) {
    int t = blockIdx.x * blockDim.x + threadIdx.x;
    int node = t >> 4;
    if (node >= n) return;
    int j = t & 15;

    float4 acc = gather_core(m, node, j);

    if (MODE == 2) {
        int b = load_idx(batch, (size_t)node, g_is64);
        float* dst = g_pool + b * 64 + j * 4;
        asm volatile("red.global.add.v4.f32 [%0], {%1,%2,%3,%4};"
                     :: "l"(dst), "f"(acc.x), "f"(acc.y), "f"(acc.z), "f"(acc.w)
                     : "memory");
    } else {
        if (MODE == 1) {
            acc.x = fmaxf(acc.x, 0.f); acc.y = fmaxf(acc.y, 0.f);
            acc.z = fmaxf(acc.z, 0.f); acc.w = fmaxf(acc.w, 0.f);
        }
        __half2 p0 = __floats2half2_rn(acc.x, acc.y);
        __half2 p1 = __floats2half2_rn(acc.z, acc.w);
        out16[(size_t)node * 16 + j] =
            make_uint2(*reinterpret_cast<unsigned*>(&p0), *reinterpret_cast<unsigned*>(&p1));
    }
}

// ---------------------------------------------------------------------------
// Head: out[g,o] = (pool[g,:]/max(cnt,1)) @ Wc[:,o]   -> [256,16]
// ---------------------------------------------------------------------------
__global__ void final_kernel(float* __restrict__ out) {
    int t = blockIdx.x * blockDim.x + threadIdx.x;
    if (t >= NG * 16) return;
    int g = t >> 4, o = t & 15;
    float inv = 1.0f / fmaxf(g_cnt[g], 1.0f);
    float acc = 0.f;
    #pragma unroll
    for (int k = 0; k < 64; k++)
        acc = fmaf(g_pool[g * 64 + k], g_wc[k * 16 + o], acc);
    out[t] = acc * inv;
}

// ---------------------------------------------------------------------------
extern "C" void kernel_launch(void* const* d_in, const int* in_sizes, int n_in,
                              void* d_out, int out_size) {
    const float* x    = (const float*)d_in[0];
    const float* W1   = (const float*)d_in[1];
    const float* W2   = (const float*)d_in[2];
    const float* W3   = (const float*)d_in[3];
    const float* Wlin = (const float*)d_in[4];
    const void*  ei   = d_in[5];
    const void*  bat  = d_in[6];

    const int n = in_sizes[0] / 128;   // nodes
    const int E = in_sizes[5] / 2;     // edges

    uint2 *d_bufA, *d_bufB, *d_bufC;
    cudaGetSymbolAddress((void**)&d_bufA, g_bufA);
    cudaGetSymbolAddress((void**)&d_bufB, g_bufB);
    cudaGetSymbolAddress((void**)&d_bufC, g_bufC);

    const int mmw_blocks = (n + 127) / 128;
    const int e_blocks   = (E + 255) / 256;
    const int h_blocks   = (E + 1023) / 1024;      // 4 edges/thread
    const int cnt_blocks = (n + 255) / 256;
    const int g_blocks   = (n * 16 + 255) / 256;   // 16 lanes/node
    const int nblk       = (n + 1023) / 1024;

    // Main: init (detect + zero). Side work depends on is64/zeroed cnt.
    init_kernel<<<1 + cnt_blocks, 256>>>((const unsigned int*)ei, n);

    // Fork after init: side branch runs mm1 (feeds gather1) then count+Wc
    // (feeds only final_kernel), overlapping the CSR build and the gathers.
    cudaEventRecord(g_side.fork, 0);
    cudaStreamWaitEvent(g_side.s, g_side.fork, 0);
    mmw_kernel<128, false, false><<<mmw_blocks, 256, 0, g_side.s>>>(x, W1, d_bufA, n);
    cudaEventRecord(g_side.join_mm1, g_side.s);
    side_misc_kernel<<<cnt_blocks + 4, 256, 0, g_side.s>>>(W3, Wlin, bat, n, cnt_blocks);
    cudaEventRecord(g_side.join_misc, g_side.s);

    // Main branch: lean CSR build chain.
    hist_kernel<<<h_blocks, 256>>>(ei, E);
    blocksum_kernel<<<nblk, 256>>>(n);
    writeptr_kernel<<<nblk, 256>>>(n, E);
    fill_kernel<<<e_blocks, 256>>>(ei, E);

    // Join mm1 before gather1 (needs CSR + m1).
    cudaStreamWaitEvent(0, g_side.join_mm1, 0);

    // Layer 1: r1 = fp16(relu(agg(m1)))
    gather_kernel<1><<<g_blocks, 256>>>(d_bufA, d_bufB, n, bat);

    // Layer 2: t2 = fp16(agg(r1)); h2 = fp16(relu(t2 @ W2)) on tensor cores
    gather_kernel<0><<<g_blocks, 256>>>(d_bufB, d_bufC, n, bat);
    mmw_kernel<64, true, true><<<mmw_blocks, 256>>>(d_bufC, W2, d_bufA, n);

    // Layer 3 + pool (linearity): pool[g] += agg(h2)[node]
    gather_kernel<2><<<g_blocks, 256>>>(d_bufA, nullptr, n, bat);

    // Join count/Wc, then head: out = (pool/cnt) @ (W3 @ Wlin)
    cudaStreamWaitEvent(0, g_side.join_misc, 0);
    final_kernel<<<16, 256>>>((float*)d_out);
}